// round 3
// baseline (speedup 1.0000x reference)
#include <cuda_runtime.h>

// Problem constants
#define TT    4096
#define EMB   1024
#define H2    512
#define G4    2048       // 4 * H2
#define NTAGS 5
#define START 3
#define STOP  4
#define NEGV  -10000.0f

// Recurrence parallelization: 64 CTAs per direction, 8 hidden units each
#define NCTA  64
#define HPER  8
#define FLAGSTRIDE 32    // ints -> 128B per flag line

// -------------------- scratch (static device globals; no allocs) ------------
__device__ float d_xs[TT * EMB];              // embedded inputs (16 MB)
__device__ float d_G[2][TT * G4];             // input-gate preactivations (64 MB)
__device__ float d_h[2][TT * H2];             // hidden states (16 MB)
__device__ float d_feats[TT * NTAGS];         // tag scores
__device__ int   d_flag[2][NCTA * FLAGSTRIDE];// per-slice progress flags

// -------------------- helpers ----------------------------------------------
__device__ __forceinline__ int ld_acq(const int* p) {
    int v;
    asm volatile("ld.acquire.gpu.global.b32 %0, [%1];" : "=r"(v) : "l"(p) : "memory");
    return v;
}
__device__ __forceinline__ void st_rel(int* p, int v) {
    asm volatile("st.release.gpu.global.b32 [%0], %1;" :: "l"(p), "r"(v) : "memory");
}
__device__ __forceinline__ float sigmoidf(float x) {
    return 1.0f / (1.0f + expf(-x));
}

// -------------------- kernel: zero flags -------------------------------------
__global__ void k_zero() {
    int i = blockIdx.x * blockDim.x + threadIdx.x;
    if (i < 2 * NCTA * FLAGSTRIDE) ((int*)d_flag)[i] = 0;
}

// -------------------- kernel: embedding gather ------------------------------
__global__ void k_gather(const int* __restrict__ sent,
                         const float* __restrict__ embed) {
    int t = blockIdx.x;
    int row = sent[t];
    const float4* src = (const float4*)(embed + (size_t)row * EMB);
    float4* dst = (float4*)(d_xs + (size_t)t * EMB);
    dst[threadIdx.x] = src[threadIdx.x];   // 256 threads * float4 = 1024 floats
}

// -------------------- kernel: input GEMM  G = xs @ Wih^T + (bih+bhh) --------
// C tile 128x128, K tile 16, 256 threads, 8x8 register blocking, double-buffered
// smem. dir==1 consumes xs in reversed time order (backward LSTM).
__global__ __launch_bounds__(256) void k_gemm(
    const float* __restrict__ Wf, const float* __restrict__ Wb,
    const float* __restrict__ bihf, const float* __restrict__ bhhf,
    const float* __restrict__ bihb, const float* __restrict__ bhhb) {
    int dir = blockIdx.z;
    const float* W  = dir ? Wb   : Wf;
    const float* b1 = dir ? bihb : bihf;
    const float* b2 = dir ? bhhb : bhhf;
    float* Gp = d_G[dir];

    __shared__ float As[2][16 * 128];
    __shared__ float Bs[2][16 * 128];

    int tid = threadIdx.x;
    int m0 = blockIdx.y * 128;
    int n0 = blockIdx.x * 128;
    int ty = tid >> 4, tx = tid & 15;

    // loader slots: f = tid + h*256, row = f>>2, kq = f&3
    int lrow[2], lkq[2], lsrcA[2];
#pragma unroll
    for (int h = 0; h < 2; h++) {
        int f = tid + h * 256;
        lrow[h] = f >> 2; lkq[h] = f & 3;
        int srcRow = m0 + lrow[h];
        if (dir) srcRow = TT - 1 - srcRow;
        lsrcA[h] = srcRow;
    }

    float acc[8][8];
#pragma unroll
    for (int i = 0; i < 8; i++)
#pragma unroll
        for (int j = 0; j < 8; j++) acc[i][j] = 0.0f;

    // prologue: tile 0 -> buffer 0
#pragma unroll
    for (int h = 0; h < 2; h++) {
        float4 va = *(const float4*)(d_xs + (size_t)lsrcA[h] * EMB + lkq[h] * 4);
        float4 vb = *(const float4*)(W + (size_t)(n0 + lrow[h]) * EMB + lkq[h] * 4);
        As[0][(lkq[h]*4+0)*128 + lrow[h]] = va.x;
        As[0][(lkq[h]*4+1)*128 + lrow[h]] = va.y;
        As[0][(lkq[h]*4+2)*128 + lrow[h]] = va.z;
        As[0][(lkq[h]*4+3)*128 + lrow[h]] = va.w;
        Bs[0][(lkq[h]*4+0)*128 + lrow[h]] = vb.x;
        Bs[0][(lkq[h]*4+1)*128 + lrow[h]] = vb.y;
        Bs[0][(lkq[h]*4+2)*128 + lrow[h]] = vb.z;
        Bs[0][(lkq[h]*4+3)*128 + lrow[h]] = vb.w;
    }
    __syncthreads();

    for (int kt = 0; kt < EMB / 16; kt++) {
        int p = kt & 1;
        float4 va[2], vb[2];
        if (kt < EMB / 16 - 1) {
            int k0 = (kt + 1) * 16;
#pragma unroll
            for (int h = 0; h < 2; h++) {
                va[h] = *(const float4*)(d_xs + (size_t)lsrcA[h] * EMB + k0 + lkq[h] * 4);
                vb[h] = *(const float4*)(W + (size_t)(n0 + lrow[h]) * EMB + k0 + lkq[h] * 4);
            }
        }
#pragma unroll
        for (int k = 0; k < 16; k++) {
            float a[8], bb[8];
#pragma unroll
            for (int i = 0; i < 8; i++) a[i]  = As[p][k * 128 + ty * 8 + i];
#pragma unroll
            for (int j = 0; j < 8; j++) bb[j] = Bs[p][k * 128 + tx * 8 + j];
#pragma unroll
            for (int i = 0; i < 8; i++)
#pragma unroll
                for (int j = 0; j < 8; j++) acc[i][j] += a[i] * bb[j];
        }
        if (kt < EMB / 16 - 1) {
            int q = 1 - p;
#pragma unroll
            for (int h = 0; h < 2; h++) {
                As[q][(lkq[h]*4+0)*128 + lrow[h]] = va[h].x;
                As[q][(lkq[h]*4+1)*128 + lrow[h]] = va[h].y;
                As[q][(lkq[h]*4+2)*128 + lrow[h]] = va[h].z;
                As[q][(lkq[h]*4+3)*128 + lrow[h]] = va[h].w;
                Bs[q][(lkq[h]*4+0)*128 + lrow[h]] = vb[h].x;
                Bs[q][(lkq[h]*4+1)*128 + lrow[h]] = vb[h].y;
                Bs[q][(lkq[h]*4+2)*128 + lrow[h]] = vb[h].z;
                Bs[q][(lkq[h]*4+3)*128 + lrow[h]] = vb[h].w;
            }
            __syncthreads();
        }
    }

    float bias[8];
#pragma unroll
    for (int j = 0; j < 8; j++) {
        int n = n0 + tx * 8 + j;
        bias[j] = b1[n] + b2[n];
    }
#pragma unroll
    for (int i = 0; i < 8; i++) {
        int m = m0 + ty * 8 + i;
#pragma unroll
        for (int j = 0; j < 8; j++) {
            int n = n0 + tx * 8 + j;
            Gp[(size_t)m * G4 + n] = acc[i][j] + bias[j];
        }
    }
}

// -------------------- kernel: persistent LSTM recurrence --------------------
// grid = 128 CTAs (64 per dir), 512 threads. CTA owns 8 hidden units = 32 gate
// rows; Whh slice in registers (32 floats/thread). G precomputed. Barrier via
// per-slice monotonic flags (distinct 128B lines, st.release / ld.acquire).
__global__ void __launch_bounds__(512, 1) k_recur(
    const float* __restrict__ Whh_f, const float* __restrict__ Whh_b,
    const float* __restrict__ h0, const float* __restrict__ c0) {
    int dir   = blockIdx.x >> 6;
    int slice = blockIdx.x & 63;
    int hbase = slice * HPER;
    const float* Whh = dir ? Whh_b : Whh_f;
    const float* Gd = d_G[dir];
    float* hout = d_h[dir];
    int* flags = d_flag[dir];

    int tid = threadIdx.x;
    int warp = tid >> 5, lane = tid & 31;

    // this warp's 2 gate rows
    int rows[2];
#pragma unroll
    for (int i = 0; i < 2; i++) {
        int r = 2 * warp + i;
        rows[i] = (r >> 3) * H2 + hbase + (r & 7);
    }
    // Whh slice: k = q*128 + lane*4 + m
    float whh[2][16];
#pragma unroll
    for (int i = 0; i < 2; i++)
#pragma unroll
        for (int q = 0; q < 4; q++) {
            float4 v = *(const float4*)(Whh + (size_t)rows[i] * H2 + q * 128 + lane * 4);
            whh[i][q*4+0] = v.x; whh[i][q*4+1] = v.y;
            whh[i][q*4+2] = v.z; whh[i][q*4+3] = v.w;
        }

    __shared__ __align__(16) float sh[H2];
    __shared__ float rec_s[32];

    const int* myflag = &flags[(tid >> 3) * FLAGSTRIDE];
    int* ourflag = &flags[slice * FLAGSTRIDE];

    float cj = 0.0f;
    float gv0 = 0.f, gv1 = 0.f, gv2 = 0.f, gv3 = 0.f;
    bool actv = (warp == 0) && (lane < HPER);
    if (actv) {
        cj = c0[dir * H2 + hbase + lane];
        gv0 = Gd[(size_t)0 * G4 + 0*H2 + hbase + lane];
        gv1 = Gd[(size_t)0 * G4 + 1*H2 + hbase + lane];
        gv2 = Gd[(size_t)0 * G4 + 2*H2 + hbase + lane];
        gv3 = Gd[(size_t)0 * G4 + 3*H2 + hbase + lane];
    }

    for (int t = 0; t < TT; t++) {
        // prefetch next-step G (off critical path)
        float ngv0 = 0.f, ngv1 = 0.f, ngv2 = 0.f, ngv3 = 0.f;
        if (actv && t + 1 < TT) {
            const float* Gn = Gd + (size_t)(t + 1) * G4;
            ngv0 = Gn[0*H2 + hbase + lane];
            ngv1 = Gn[1*H2 + hbase + lane];
            ngv2 = Gn[2*H2 + hbase + lane];
            ngv3 = Gn[3*H2 + hbase + lane];
        }

        // wait for the slice producing my sh element, then stage it
        while (ld_acq(myflag) < t) { }
        sh[tid] = (t == 0) ? h0[dir * H2 + tid]
                           : hout[(size_t)(t - 1) * H2 + tid];
        __syncthreads();

        // recurrent GEMV
        float a0 = 0.0f, a1 = 0.0f;
#pragma unroll
        for (int q = 0; q < 4; q++) {
            float4 hv = *(const float4*)(sh + q * 128 + lane * 4);
            a0 += whh[0][q*4+0]*hv.x + whh[0][q*4+1]*hv.y + whh[0][q*4+2]*hv.z + whh[0][q*4+3]*hv.w;
            a1 += whh[1][q*4+0]*hv.x + whh[1][q*4+1]*hv.y + whh[1][q*4+2]*hv.z + whh[1][q*4+3]*hv.w;
        }
#pragma unroll
        for (int off = 16; off > 0; off >>= 1) {
            a0 += __shfl_xor_sync(0xffffffffu, a0, off);
            a1 += __shfl_xor_sync(0xffffffffu, a1, off);
        }
        if (lane == 0) { rec_s[2*warp] = a0; rec_s[2*warp+1] = a1; }
        __syncthreads();

        // activation + h write + flag release (warp 0)
        if (warp == 0) {
            if (lane < HPER) {
                float gi = rec_s[0*HPER + lane] + gv0;
                float gf = rec_s[1*HPER + lane] + gv1;
                float gg = rec_s[2*HPER + lane] + gv2;
                float go = rec_s[3*HPER + lane] + gv3;
                cj = sigmoidf(gf) * cj + sigmoidf(gi) * tanhf(gg);
                float hj = sigmoidf(go) * tanhf(cj);
                hout[(size_t)t * H2 + hbase + lane] = hj;
                gv0 = ngv0; gv1 = ngv1; gv2 = ngv2; gv3 = ngv3;
            }
            __syncwarp();
            if (lane == 0) st_rel(ourflag, t + 1);
        }
    }
}

// -------------------- kernel: output projection feats = [hf|hb] @ Wout^T ----
__global__ void k_feats(const float* __restrict__ Wout,
                        const float* __restrict__ bout) {
    int t = blockIdx.x;
    int n = threadIdx.x >> 5;              // 5 warps -> 5 tags
    int lane = threadIdx.x & 31;
    const float* hf = d_h[0] + (size_t)t * H2;
    const float* hb = d_h[1] + (size_t)(TT - 1 - t) * H2;
    float s = 0.0f;
    const float* Wn = Wout + (size_t)n * (2 * H2);
#pragma unroll 4
    for (int k = lane; k < H2; k += 32) s += Wn[k] * hf[k];
#pragma unroll 4
    for (int k = lane; k < H2; k += 32) s += Wn[H2 + k] * hb[k];
#pragma unroll
    for (int off = 16; off > 0; off >>= 1) s += __shfl_xor_sync(0xffffffffu, s, off);
    if (lane == 0) d_feats[t * NTAGS + n] = s + bout[n];
}

// -------------------- kernel: Viterbi + backtrace (single CTA) --------------
__global__ void k_viterbi(const float* __restrict__ trans,
                          float* __restrict__ out, int out_size) {
    extern __shared__ float smem[];
    float* sfeat = smem;                                      // TT*NTAGS floats
    unsigned char* sbp = (unsigned char*)(smem + TT * NTAGS); // TT*NTAGS bytes
    __shared__ float fv[NTAGS];
    __shared__ float fvn[NTAGS];

    int tid = threadIdx.x;
    const float4* d4 = (const float4*)d_feats;
    float4* s4 = (float4*)sfeat;
    for (int i = tid; i < (TT * NTAGS) / 4; i += blockDim.x) s4[i] = d4[i];
    __syncthreads();

    if (tid < 32) {
        int n = tid;
        float tr[NTAGS];
        if (n < NTAGS) {
#pragma unroll
            for (int p = 0; p < NTAGS; p++) tr[p] = trans[n * NTAGS + p];
            fv[n] = (n == START) ? 0.0f : NEGV;
        }
        __syncwarp();
        for (int t = 0; t < TT; t++) {
            if (n < NTAGS) {
                float best = fv[0] + tr[0];
                int bp = 0;
#pragma unroll
                for (int p = 1; p < NTAGS; p++) {
                    float s = fv[p] + tr[p];
                    if (s > best) { best = s; bp = p; }
                }
                fvn[n] = best + sfeat[t * NTAGS + n];
                sbp[t * NTAGS + n] = (unsigned char)bp;
            }
            __syncwarp();
            if (n < NTAGS) fv[n] = fvn[n];
            __syncwarp();
        }
        if (n == 0) {
            float best = fv[0] + trans[STOP * NTAGS + 0];
            int bt = 0;
#pragma unroll
            for (int p = 1; p < NTAGS; p++) {
                float s = fv[p] + trans[STOP * NTAGS + p];
                if (s > best) { best = s; bt = p; }
            }
            if (out_size > 0) out[0] = best;
            int tag = bt;
            if (1 + (TT - 1) < out_size) out[1 + (TT - 1)] = (float)tag;
            for (int t = TT - 1; t >= 1; t--) {
                tag = sbp[t * NTAGS + tag];
                if (t < out_size) out[t] = (float)tag;
            }
        }
    }
}

// -------------------- launcher ----------------------------------------------
extern "C" void kernel_launch(void* const* d_in, const int* in_sizes, int n_in,
                              void* d_out, int out_size) {
    const int*   sent  = (const int*)d_in[0];
    const float* h0    = (const float*)d_in[1];
    const float* c0    = (const float*)d_in[2];
    const float* embed = (const float*)d_in[3];
    const float* Wih_f = (const float*)d_in[4];
    const float* Whh_f = (const float*)d_in[5];
    const float* bih_f = (const float*)d_in[6];
    const float* bhh_f = (const float*)d_in[7];
    const float* Wih_b = (const float*)d_in[8];
    const float* Whh_b = (const float*)d_in[9];
    const float* bih_b = (const float*)d_in[10];
    const float* bhh_b = (const float*)d_in[11];
    const float* Wout  = (const float*)d_in[12];
    const float* bout  = (const float*)d_in[13];
    const float* trans = (const float*)d_in[14];
    float* out = (float*)d_out;

    k_zero<<<16, 256>>>();
    k_gather<<<TT, 256>>>(sent, embed);
    dim3 gg(G4 / 128, TT / 128, 2);
    k_gemm<<<gg, 256>>>(Wih_f, Wih_b, bih_f, bhh_f, bih_b, bhh_b);
    k_recur<<<2 * NCTA, 512>>>(Whh_f, Whh_b, h0, c0);
    k_feats<<<TT, 160>>>(Wout, bout);

    int vit_smem = TT * NTAGS * (int)sizeof(float) + TT * NTAGS;  // 102400 B
    cudaFuncSetAttribute(k_viterbi, cudaFuncAttributeMaxDynamicSharedMemorySize,
                         vit_smem);
    k_viterbi<<<1, 128, vit_smem>>>(trans, out, out_size);
}